// round 2
// baseline (speedup 1.0000x reference)
#include <cuda_runtime.h>
#include <cstdint>

// FPS B=16, N=65536, S=2048. Cluster of 8 CTAs per batch, 1024 thr/CTA.
// Negated coords SoA in smem; f32x2 packed distance math (bit-identical IEEE);
// value-only max in loop + equality rescan for exact first-index argmax;
// redux.sync + smem atomics for CTA reduce; DSMEM push + mbarrier for cluster
// reduce (winner coords ride along with the key -> no global fetch).

#define NBATCH   16
#define NPTS     65536
#define NSAMP    2048
#define CLUSTER  8
#define NPC      (NPTS / CLUSTER)     // 8192
#define THREADS  1024
#define PPT      (NPC / THREADS)      // 8
#define GROUPS   (PPT / 4)            // 2

typedef unsigned long long u64;

struct Slot { u64 key; float x; float y; float z; };   // 24B, key@0 x@8 y@12 z@16

struct __align__(16) Smem {
    float x[NPC];              // negated coords
    float y[NPC];
    float z[NPC];
    Slot  slots[2][CLUSTER];   // parity-double-buffered cluster exchange
    unsigned cta_vmax[2];      // float bits of CTA max (>=0)
    unsigned cta_idx[2];       // min local index matching cta_vmax
    u64   mbar;
};

__device__ __forceinline__ uint32_t smem_u32(const void* p) {
    return (uint32_t)__cvta_generic_to_shared(p);
}
__device__ __forceinline__ u64 pk2(float lo, float hi) {
    u64 r; asm("mov.b64 %0, {%1, %2};" : "=l"(r) : "f"(lo), "f"(hi)); return r;
}
__device__ __forceinline__ void upk2(float& lo, float& hi, u64 v) {
    asm("mov.b64 {%0, %1}, %2;" : "=f"(lo), "=f"(hi) : "l"(v));
}
__device__ __forceinline__ u64 add2(u64 a, u64 b) {
    u64 r; asm("add.rn.f32x2 %0, %1, %2;" : "=l"(r) : "l"(a), "l"(b)); return r;
}
__device__ __forceinline__ u64 mul2(u64 a, u64 b) {
    u64 r; asm("mul.rn.f32x2 %0, %1, %2;" : "=l"(r) : "l"(a), "l"(b)); return r;
}

__global__ void __cluster_dims__(CLUSTER, 1, 1) __launch_bounds__(THREADS, 1)
fps_kernel(const float* __restrict__ pc, float* __restrict__ out)
{
    extern __shared__ Smem sm[];
    Smem& s = *sm;

    const int tid  = threadIdx.x;
    const int lane = tid & 31;
    const int rank = blockIdx.x & (CLUSTER - 1);
    const int b    = blockIdx.x >> 3;

    const float* __restrict__ base = pc + (size_t)b * NPTS * 3;

    // ---- prologue: stage negated coords (SoA), init slots + mbarrier ----
    for (int i = tid; i < NPC; i += THREADS) {
        int gi = rank * NPC + i;
        s.x[i] = -base[gi * 3 + 0];
        s.y[i] = -base[gi * 3 + 1];
        s.z[i] = -base[gi * 3 + 2];
    }
    if (tid == 0) {
        s.cta_vmax[0] = 0u; s.cta_vmax[1] = 0u;
        s.cta_idx[0] = 0xffffffffu; s.cta_idx[1] = 0xffffffffu;
        asm volatile("mbarrier.init.shared.b64 [%0], %1;"
                     :: "r"(smem_u32(&s.mbar)), "r"(CLUSTER) : "memory");
    }

    float closest[PPT];
    #pragma unroll
    for (int i = 0; i < PPT; i++) closest[i] = __int_as_float(0x7f800000);

    float fx = base[0], fy = base[1], fz = base[2];   // initial selection: point 0
    u64 sxx = pk2(fx, fx), syy = pk2(fy, fy), szz = pk2(fz, fz);

    __syncthreads();
    asm volatile("barrier.cluster.arrive.aligned;" ::: "memory");
    asm volatile("barrier.cluster.wait.aligned;"   ::: "memory");

    const uint32_t mb_addr = smem_u32(&s.mbar);

    for (int it = 0; it < NSAMP; ++it) {
        const int p = it & 1;

        // ---- distance update + running min; track max VALUE only ----
        float vmax = 0.0f;
        #pragma unroll
        for (int g = 0; g < GROUPS; ++g) {
            const int bi = g * (THREADS * 4) + tid * 4;
            float4 xv = *reinterpret_cast<const float4*>(&s.x[bi]);
            float4 yv = *reinterpret_cast<const float4*>(&s.y[bi]);
            float4 zv = *reinterpret_cast<const float4*>(&s.z[bi]);
            {   // pair (0,1)
                u64 dx = add2(sxx, pk2(xv.x, xv.y));
                u64 dy = add2(syy, pk2(yv.x, yv.y));
                u64 dz = add2(szz, pk2(zv.x, zv.y));
                u64 d  = add2(add2(mul2(dx, dx), mul2(dy, dy)), mul2(dz, dz));
                float d0, d1; upk2(d0, d1, d);
                float c0 = fminf(closest[g*4+0], d0); closest[g*4+0] = c0;
                float c1 = fminf(closest[g*4+1], d1); closest[g*4+1] = c1;
                vmax = fmaxf(vmax, c0); vmax = fmaxf(vmax, c1);
            }
            {   // pair (2,3)
                u64 dx = add2(sxx, pk2(xv.z, xv.w));
                u64 dy = add2(syy, pk2(yv.z, yv.w));
                u64 dz = add2(szz, pk2(zv.z, zv.w));
                u64 d  = add2(add2(mul2(dx, dx), mul2(dy, dy)), mul2(dz, dz));
                float d0, d1; upk2(d0, d1, d);
                float c0 = fminf(closest[g*4+2], d0); closest[g*4+2] = c0;
                float c1 = fminf(closest[g*4+3], d1); closest[g*4+3] = c1;
                vmax = fmaxf(vmax, c0); vmax = fmaxf(vmax, c1);
            }
        }

        // ---- CTA max value: redux (warp) + atomicMax (CTA) ----
        unsigned wb;
        asm("redux.sync.max.u32 %0, %1, 0xffffffff;"
            : "=r"(wb) : "r"(__float_as_uint(vmax)));
        if (lane == 0) atomicMax(&s.cta_vmax[p], wb);
        __syncthreads();                               // sync1
        const unsigned Mb = s.cta_vmax[p];
        if (tid == 0) {                                // reset other parity for next iter
            s.cta_vmax[1 - p] = 0u;
            s.cta_idx[1 - p]  = 0xffffffffu;
        }

        // ---- exact first-index: rescan registers for == Mb, atomicMin ----
        unsigned my = 0xffffffffu;
        #pragma unroll
        for (int g = 0; g < GROUPS; ++g) {
            #pragma unroll
            for (int j = 0; j < 4; ++j) {
                if (__float_as_uint(closest[g*4+j]) == Mb && my == 0xffffffffu)
                    my = (unsigned)(g * (THREADS*4) + tid * 4 + j);
            }
        }
        if (my != 0xffffffffu) atomicMin(&s.cta_idx[p], my);
        __syncthreads();                               // sync2

        // ---- publish {key, coords} to all 8 peers; arrive on their mbarriers ----
        if (tid < CLUSTER) {
            unsigned li   = s.cta_idx[p];
            unsigned gidx = (unsigned)rank * NPC + li;
            u64 key = ((u64)Mb << 32) | (u64)(~gidx);  // tie -> smaller gidx wins
            float cx = -s.x[li], cy = -s.y[li], cz = -s.z[li];
            u64 xy = pk2(cx, cy);
            uint32_t sl = smem_u32(&s.slots[p][rank]);
            uint32_t rs, rb;
            asm volatile("mapa.shared::cluster.u32 %0, %1, %2;" : "=r"(rs) : "r"(sl),      "r"(tid));
            asm volatile("mapa.shared::cluster.u32 %0, %1, %2;" : "=r"(rb) : "r"(mb_addr), "r"(tid));
            asm volatile("st.shared::cluster.b64 [%0],    %1;" :: "r"(rs), "l"(key) : "memory");
            asm volatile("st.shared::cluster.b64 [%0+8],  %1;" :: "r"(rs), "l"(xy)  : "memory");
            asm volatile("st.shared::cluster.f32 [%0+16], %1;" :: "r"(rs), "f"(cz)  : "memory");
            asm volatile("mbarrier.arrive.release.cluster.shared::cluster.b64 _, [%0];"
                         :: "r"(rb) : "memory");
        }

        // ---- wait for all 8 publishes (acquire, cluster scope) ----
        asm volatile(
            "{\n\t.reg .pred P;\n"
            "W%=:\n\t"
            "mbarrier.try_wait.parity.acquire.cluster.shared::cta.b64 P, [%0], %1, 0x989680;\n\t"
            "@P bra.uni D%=;\n\t"
            "bra.uni W%=;\n"
            "D%=:\n\t}"
            :: "r"(mb_addr), "r"(p) : "memory");

        // ---- every thread scans the 8 slots; winner coords are local ----
        const Slot* sl = s.slots[p];
        u64 bk = sl[0].key;
        int br = 0;
        #pragma unroll
        for (int r = 1; r < CLUSTER; ++r) {
            u64 kr = sl[r].key;
            if (kr > bk) { bk = kr; br = r; }
        }
        float nsx = sl[br].x, nsy = sl[br].y, nsz = sl[br].z;

        if (rank == 0 && tid == 0) {
            float* o = out + ((size_t)b * NSAMP + it) * 3;
            o[0] = nsx; o[1] = nsy; o[2] = nsz;
        }

        sxx = pk2(nsx, nsx); syy = pk2(nsy, nsy); szz = pk2(nsz, nsz);
    }
}

extern "C" void kernel_launch(void* const* d_in, const int* in_sizes, int n_in,
                              void* d_out, int out_size)
{
    (void)in_sizes; (void)n_in; (void)out_size;
    const float* pc  = (const float*)d_in[0];
    float*       out = (float*)d_out;

    static bool attr_set = false;
    if (!attr_set) {
        cudaFuncSetAttribute(fps_kernel,
                             cudaFuncAttributeMaxDynamicSharedMemorySize,
                             (int)sizeof(Smem));
        attr_set = true;
    }
    fps_kernel<<<NBATCH * CLUSTER, THREADS, sizeof(Smem)>>>(pc, out);
}

// round 4
// speedup vs baseline: 1.2117x; 1.2117x over previous
#include <cuda_runtime.h>
#include <cstdint>

// FPS B=16, N=65536, S=2048, out = coords of selected (B,S,3) f32.
// Cluster of 8 CTAs/batch, 512 thr/CTA, coords SoA in smem, closest[] in regs.
// Value-only max in hot loop (redux.sync) + equality rescan for exact
// first-index argmax; DSMEM push + mbarrier cluster exchange (winner coords
// ride with the key). One __syncthreads per iteration.

#define NBATCH   16
#define NPTS     65536
#define NSAMP    2048
#define CLUSTER  8
#define NPC      (NPTS / CLUSTER)     // 8192
#define THREADS  512
#define NWARPS   (THREADS / 32)       // 16
#define PPT      (NPC / THREADS)      // 16
#define GROUPS   (PPT / 4)            // 4

typedef unsigned long long u64;

// 32-byte slot: key @0 (8-aligned), xy packed @8 (8-aligned), z @16.
struct __align__(16) Slot { u64 key; u64 xy; float z; float pad[3]; };

struct __align__(16) Smem {
    float x[NPC];
    float y[NPC];
    float z[NPC];
    u64   wkey[NWARPS];          // per-warp packed (valBits<<32)|~localIdx
    Slot  slots[2][CLUSTER];     // parity-double-buffered cluster exchange
    u64   mbar;
};

__device__ __forceinline__ uint32_t smem_u32(const void* p) {
    return (uint32_t)__cvta_generic_to_shared(p);
}
__device__ __forceinline__ u64 pk2(float lo, float hi) {
    u64 r; asm("mov.b64 %0, {%1, %2};" : "=l"(r) : "f"(lo), "f"(hi)); return r;
}
__device__ __forceinline__ void upk2(float& lo, float& hi, u64 v) {
    asm("mov.b64 {%0, %1}, %2;" : "=f"(lo), "=f"(hi) : "l"(v));
}

__global__ void __cluster_dims__(CLUSTER, 1, 1) __launch_bounds__(THREADS, 1)
fps_kernel(const float* __restrict__ pc, float* __restrict__ out)
{
    extern __shared__ Smem sm[];
    Smem& s = *sm;

    const int tid  = threadIdx.x;
    const int lane = tid & 31;
    const int warp = tid >> 5;
    const int rank = blockIdx.x & (CLUSTER - 1);
    const int b    = blockIdx.x >> 3;

    const float* __restrict__ base = pc + (size_t)b * NPTS * 3;

    // ---- prologue ----
    for (int i = tid; i < NPC; i += THREADS) {
        int gi = rank * NPC + i;
        s.x[i] = base[gi * 3 + 0];
        s.y[i] = base[gi * 3 + 1];
        s.z[i] = base[gi * 3 + 2];
    }
    if (tid == 0) {
        asm volatile("mbarrier.init.shared.b64 [%0], %1;"
                     :: "r"(smem_u32(&s.mbar)), "r"(CLUSTER) : "memory");
    }

    float closest[PPT];
    #pragma unroll
    for (int i = 0; i < PPT; i++) closest[i] = __int_as_float(0x7f800000);

    float sx = base[0], sy = base[1], sz = base[2];   // initial selection: point 0

    __syncthreads();
    asm volatile("barrier.cluster.arrive.aligned;" ::: "memory");
    asm volatile("barrier.cluster.wait.aligned;"   ::: "memory");

    const uint32_t mb_addr = smem_u32(&s.mbar);

    for (int it = 0; it < NSAMP; ++it) {
        const int p = it & 1;

        // ---- distance update + running min; value-only max ----
        float vmax = 0.0f;
        #pragma unroll
        for (int g = 0; g < GROUPS; ++g) {
            const int bi = g * (THREADS * 4) + tid * 4;
            float4 xv = *reinterpret_cast<const float4*>(&s.x[bi]);
            float4 yv = *reinterpret_cast<const float4*>(&s.y[bi]);
            float4 zv = *reinterpret_cast<const float4*>(&s.z[bi]);
            float xs[4] = {xv.x, xv.y, xv.z, xv.w};
            float ys[4] = {yv.x, yv.y, yv.z, yv.w};
            float zs[4] = {zv.x, zv.y, zv.z, zv.w};
            #pragma unroll
            for (int j = 0; j < 4; ++j) {
                // match XLA: sub, square (no FMA), left-assoc sum
                float dx = __fadd_rn(sx, -xs[j]);
                float dy = __fadd_rn(sy, -ys[j]);
                float dz = __fadd_rn(sz, -zs[j]);
                float d  = __fadd_rn(__fadd_rn(__fmul_rn(dx, dx), __fmul_rn(dy, dy)),
                                     __fmul_rn(dz, dz));
                float c = fminf(closest[g * 4 + j], d);
                closest[g * 4 + j] = c;
                vmax = fmaxf(vmax, c);
            }
        }

        // ---- warp reduce: redux max on float bits (all >= 0) ----
        unsigned wmax;
        asm("redux.sync.max.u32 %0, %1, 0xffffffff;"
            : "=r"(wmax) : "r"(__float_as_uint(vmax)));

        // exact first index: rescan registers for == wmax (ascending order)
        unsigned my = 0xffffffffu;
        #pragma unroll
        for (int g = 0; g < GROUPS; ++g) {
            #pragma unroll
            for (int j = 0; j < 4; ++j) {
                if (__float_as_uint(closest[g*4+j]) == wmax && my == 0xffffffffu)
                    my = (unsigned)(g * (THREADS*4) + tid * 4 + j);
            }
        }
        unsigned wmin;
        asm("redux.sync.min.u32 %0, %1, 0xffffffff;"
            : "=r"(wmin) : "r"(my));
        if (lane == 0)
            s.wkey[warp] = ((u64)wmax << 32) | (u64)(unsigned)(~wmin);
        __syncthreads();

        // ---- CTA reduce (warp 0) + push to all 8 peers ----
        if (warp == 0) {
            u64 k = (lane < NWARPS) ? s.wkey[lane] : 0ull;
            #pragma unroll
            for (int off = 8; off > 0; off >>= 1) {
                u64 o = __shfl_xor_sync(0xffffffffu, k, off);
                if (o > k) k = o;
            }
            // every lane now holds the CTA-best key
            if (lane < CLUSTER) {
                unsigned li   = ~(unsigned)k;                 // local index
                unsigned gidx = (unsigned)rank * NPC + li;    // batch-global index
                u64 ckey = (k & 0xffffffff00000000ull) | (u64)(unsigned)(~gidx);
                float cx = s.x[li], cy = s.y[li], cz = s.z[li];
                u64 xy = pk2(cx, cy);
                uint32_t sl = smem_u32(&s.slots[p][rank]);
                uint32_t rs, rb;
                asm volatile("mapa.shared::cluster.u32 %0, %1, %2;" : "=r"(rs) : "r"(sl),      "r"(lane));
                asm volatile("mapa.shared::cluster.u32 %0, %1, %2;" : "=r"(rb) : "r"(mb_addr), "r"(lane));
                asm volatile("st.shared::cluster.b64 [%0],    %1;" :: "r"(rs), "l"(ckey) : "memory");
                asm volatile("st.shared::cluster.b64 [%0+8],  %1;" :: "r"(rs), "l"(xy)   : "memory");
                asm volatile("st.shared::cluster.f32 [%0+16], %1;" :: "r"(rs), "f"(cz)   : "memory");
                asm volatile("mbarrier.arrive.release.cluster.shared::cluster.b64 _, [%0];"
                             :: "r"(rb) : "memory");
            }
        }

        // ---- wait for all 8 publishes ----
        asm volatile(
            "{\n\t.reg .pred P;\n"
            "W%=:\n\t"
            "mbarrier.try_wait.parity.acquire.cluster.shared::cta.b64 P, [%0], %1, 0x989680;\n\t"
            "@P bra.uni D%=;\n\t"
            "bra.uni W%=;\n"
            "D%=:\n\t}"
            :: "r"(mb_addr), "r"(p) : "memory");

        // ---- scan 8 local slots; winner coords are local ----
        const Slot* sl = s.slots[p];
        u64 bk = sl[0].key;
        int br = 0;
        #pragma unroll
        for (int r = 1; r < CLUSTER; ++r) {
            u64 kr = sl[r].key;
            if (kr > bk) { bk = kr; br = r; }
        }
        float nsx, nsy;
        upk2(nsx, nsy, sl[br].xy);
        float nsz = sl[br].z;

        if (rank == 0 && tid == 0) {
            float* o = out + ((size_t)b * NSAMP + it) * 3;
            o[0] = nsx; o[1] = nsy; o[2] = nsz;
        }
        sx = nsx; sy = nsy; sz = nsz;
    }
}

extern "C" void kernel_launch(void* const* d_in, const int* in_sizes, int n_in,
                              void* d_out, int out_size)
{
    (void)in_sizes; (void)n_in; (void)out_size;
    const float* pc  = (const float*)d_in[0];
    float*       out = (float*)d_out;

    static bool attr_set = false;
    if (!attr_set) {
        cudaFuncSetAttribute(fps_kernel,
                             cudaFuncAttributeMaxDynamicSharedMemorySize,
                             (int)sizeof(Smem));
        attr_set = true;
    }
    fps_kernel<<<NBATCH * CLUSTER, THREADS, sizeof(Smem)>>>(pc, out);
}

// round 6
// speedup vs baseline: 1.8330x; 1.5127x over previous
#include <cuda_runtime.h>
#include <cstdint>

// FPS B=16, N=65536, S=2048, out = coords of selected (B,S,3) f32.
// Two co-resident CTAs per SM from DIFFERENT batches hide the serial
// reduction tail. Preferred shape: cluster=16 (non-portable), 256 CTAs x 256
// threads, NPC=4096. Fallback: cluster=8, 128 CTAs x 512 threads.
// Coords SoA in smem; closest[] in regs; value-only max (redux.sync) +
// equality rescan for exact first-index argmax; DSMEM push + mbarrier
// cluster exchange (winner coords ride with the key).

#define NBATCH   16
#define NPTS     65536
#define NSAMP    2048

typedef unsigned long long u64;

// 32-byte slot: key @0 (8-aligned), xy packed @8 (8-aligned), z @16.
struct __align__(16) Slot { u64 key; u64 xy; float z; float pad[3]; };

template<int CL, int TH>
struct __align__(16) SmemT {
    static const int NPC = NPTS / CL;
    float x[NPC];
    float y[NPC];
    float z[NPC];
    u64   wkey[TH / 32];
    Slot  slots[2][CL];
    u64   mbar;
};

__device__ __forceinline__ uint32_t smem_u32(const void* p) {
    return (uint32_t)__cvta_generic_to_shared(p);
}
__device__ __forceinline__ u64 pk2(float lo, float hi) {
    u64 r; asm("mov.b64 %0, {%1, %2};" : "=l"(r) : "f"(lo), "f"(hi)); return r;
}
__device__ __forceinline__ void upk2(float& lo, float& hi, u64 v) {
    asm("mov.b64 {%0, %1}, %2;" : "=f"(lo), "=f"(hi) : "l"(v));
}

template<int CL, int TH>
__global__ void __launch_bounds__(TH, 2)
fps_kernel(const float* __restrict__ pc, float* __restrict__ out)
{
    const int NPC    = NPTS / CL;
    const int NWARPS = TH / 32;
    const int PPT    = NPC / TH;      // 16 in both shapes
    const int GROUPS = PPT / 4;       // 4

    extern __shared__ char smraw[];
    SmemT<CL, TH>& s = *reinterpret_cast<SmemT<CL, TH>*>(smraw);

    const int tid  = threadIdx.x;
    const int lane = tid & 31;
    const int warp = tid >> 5;
    const int rank = blockIdx.x % CL;
    const int b    = blockIdx.x / CL;

    const float* __restrict__ base = pc + (size_t)b * NPTS * 3;

    // ---- prologue ----
    for (int i = tid; i < NPC; i += TH) {
        int gi = rank * NPC + i;
        s.x[i] = base[gi * 3 + 0];
        s.y[i] = base[gi * 3 + 1];
        s.z[i] = base[gi * 3 + 2];
    }
    if (tid == 0) {
        asm volatile("mbarrier.init.shared.b64 [%0], %1;"
                     :: "r"(smem_u32(&s.mbar)), "r"(CL) : "memory");
    }

    float closest[16];
    #pragma unroll
    for (int i = 0; i < PPT; i++) closest[i] = __int_as_float(0x7f800000);

    float sx = base[0], sy = base[1], sz = base[2];   // initial selection: point 0

    __syncthreads();
    asm volatile("barrier.cluster.arrive.aligned;" ::: "memory");
    asm volatile("barrier.cluster.wait.aligned;"   ::: "memory");

    const uint32_t mb_addr = smem_u32(&s.mbar);

    for (int it = 0; it < NSAMP; ++it) {
        const int p = it & 1;

        // ---- distance update + running min; value-only max ----
        float vmax = 0.0f;
        #pragma unroll
        for (int g = 0; g < GROUPS; ++g) {
            const int bi = g * (TH * 4) + tid * 4;
            float4 xv = *reinterpret_cast<const float4*>(&s.x[bi]);
            float4 yv = *reinterpret_cast<const float4*>(&s.y[bi]);
            float4 zv = *reinterpret_cast<const float4*>(&s.z[bi]);
            float xs[4] = {xv.x, xv.y, xv.z, xv.w};
            float ys[4] = {yv.x, yv.y, yv.z, yv.w};
            float zs[4] = {zv.x, zv.y, zv.z, zv.w};
            #pragma unroll
            for (int j = 0; j < 4; ++j) {
                // match XLA: sub, square (no FMA), left-assoc sum
                float dx = __fadd_rn(sx, -xs[j]);
                float dy = __fadd_rn(sy, -ys[j]);
                float dz = __fadd_rn(sz, -zs[j]);
                float d  = __fadd_rn(__fadd_rn(__fmul_rn(dx, dx), __fmul_rn(dy, dy)),
                                     __fmul_rn(dz, dz));
                float c = fminf(closest[g * 4 + j], d);
                closest[g * 4 + j] = c;
                vmax = fmaxf(vmax, c);
            }
        }

        // ---- warp reduce: redux max on float bits (all >= 0) ----
        unsigned wmax;
        asm("redux.sync.max.u32 %0, %1, 0xffffffff;"
            : "=r"(wmax) : "r"(__float_as_uint(vmax)));

        // exact first index: min over matching indices (ascending scan)
        unsigned my = 0xffffffffu;
        #pragma unroll
        for (int g = 0; g < GROUPS; ++g) {
            #pragma unroll
            for (int j = 0; j < 4; ++j) {
                unsigned cand = (unsigned)(g * (TH * 4) + tid * 4 + j);
                if (__float_as_uint(closest[g*4+j]) == wmax)
                    my = (cand < my) ? cand : my;
            }
        }
        unsigned wmin;
        asm("redux.sync.min.u32 %0, %1, 0xffffffff;"
            : "=r"(wmin) : "r"(my));
        if (lane == 0)
            s.wkey[warp] = ((u64)wmax << 32) | (u64)(unsigned)(~wmin);
        __syncthreads();

        // ---- CTA reduce (warp 0) + push to all CL peers ----
        if (warp == 0) {
            u64 k = (lane < NWARPS) ? s.wkey[lane] : 0ull;
            #pragma unroll
            for (int off = 8; off > 0; off >>= 1) {
                u64 o = __shfl_xor_sync(0xffffffffu, k, off);
                if (o > k) k = o;
            }
            // every lane now holds the CTA-best key
            if (lane < CL) {
                unsigned li   = ~(unsigned)k;                 // local index
                unsigned gidx = (unsigned)rank * NPC + li;    // batch-global index
                u64 ckey = (k & 0xffffffff00000000ull) | (u64)(unsigned)(~gidx);
                float cx = s.x[li], cy = s.y[li], cz = s.z[li];
                u64 xy = pk2(cx, cy);
                uint32_t sl = smem_u32(&s.slots[p][rank]);
                uint32_t rs, rb;
                asm volatile("mapa.shared::cluster.u32 %0, %1, %2;" : "=r"(rs) : "r"(sl),      "r"(lane));
                asm volatile("mapa.shared::cluster.u32 %0, %1, %2;" : "=r"(rb) : "r"(mb_addr), "r"(lane));
                asm volatile("st.shared::cluster.b64 [%0],    %1;" :: "r"(rs), "l"(ckey) : "memory");
                asm volatile("st.shared::cluster.b64 [%0+8],  %1;" :: "r"(rs), "l"(xy)   : "memory");
                asm volatile("st.shared::cluster.f32 [%0+16], %1;" :: "r"(rs), "f"(cz)   : "memory");
                asm volatile("mbarrier.arrive.release.cluster.shared::cluster.b64 _, [%0];"
                             :: "r"(rb) : "memory");
            }
        }

        // ---- wait for all CL publishes ----
        asm volatile(
            "{\n\t.reg .pred P;\n"
            "W%=:\n\t"
            "mbarrier.try_wait.parity.acquire.cluster.shared::cta.b64 P, [%0], %1, 0x989680;\n\t"
            "@P bra.uni D%=;\n\t"
            "bra.uni W%=;\n"
            "D%=:\n\t}"
            :: "r"(mb_addr), "r"(p) : "memory");

        // ---- scan CL local slots; winner coords are local ----
        const Slot* sl = s.slots[p];
        u64 bk = sl[0].key;
        int br = 0;
        #pragma unroll
        for (int r = 1; r < CL; ++r) {
            u64 kr = sl[r].key;
            if (kr > bk) { bk = kr; br = r; }
        }
        float nsx, nsy;
        upk2(nsx, nsy, sl[br].xy);
        float nsz = sl[br].z;

        if (rank == 0 && tid == 0) {
            float* o = out + ((size_t)b * NSAMP + it) * 3;
            o[0] = nsx; o[1] = nsy; o[2] = nsz;
        }
        sx = nsx; sy = nsy; sz = nsz;
    }
}

extern "C" void kernel_launch(void* const* d_in, const int* in_sizes, int n_in,
                              void* d_out, int out_size)
{
    (void)in_sizes; (void)n_in; (void)out_size;
    const float* pc  = (const float*)d_in[0];
    float*       out = (float*)d_out;

    static int mode = -1;   // 16 = cluster16/256thr, 8 = cluster8/512thr
    if (mode < 0) {
        mode = 8;
        size_t sm16 = sizeof(SmemT<16, 256>);
        if (cudaFuncSetAttribute(fps_kernel<16, 256>,
                                 cudaFuncAttributeMaxDynamicSharedMemorySize,
                                 (int)sm16) == cudaSuccess &&
            cudaFuncSetAttribute(fps_kernel<16, 256>,
                                 cudaFuncAttributeNonPortableClusterSizeAllowed,
                                 1) == cudaSuccess) {
            cudaLaunchConfig_t cfg = {};
            cfg.gridDim = dim3(NBATCH * 16, 1, 1);
            cfg.blockDim = dim3(256, 1, 1);
            cfg.dynamicSmemBytes = sm16;
            cudaLaunchAttribute attrs[1];
            attrs[0].id = cudaLaunchAttributeClusterDimension;
            attrs[0].val.clusterDim = {16, 1, 1};
            cfg.attrs = attrs;
            cfg.numAttrs = 1;
            int nclusters = 0;
            if (cudaOccupancyMaxActiveClusters(&nclusters, fps_kernel<16, 256>, &cfg)
                    == cudaSuccess && nclusters >= NBATCH) {
                mode = 16;
            }
            cudaGetLastError();   // clear any sticky-free error from probing
        }
        if (mode == 8) {
            cudaFuncSetAttribute(fps_kernel<8, 512>,
                                 cudaFuncAttributeMaxDynamicSharedMemorySize,
                                 (int)sizeof(SmemT<8, 512>));
        }
    }

    if (mode == 16) {
        cudaLaunchConfig_t cfg = {};
        cfg.gridDim = dim3(NBATCH * 16, 1, 1);
        cfg.blockDim = dim3(256, 1, 1);
        cfg.dynamicSmemBytes = sizeof(SmemT<16, 256>);
        cfg.stream = 0;
        cudaLaunchAttribute attrs[1];
        attrs[0].id = cudaLaunchAttributeClusterDimension;
        attrs[0].val.clusterDim = {16, 1, 1};
        cfg.attrs = attrs;
        cfg.numAttrs = 1;
        cudaLaunchKernelEx(&cfg, fps_kernel<16, 256>, pc, out);
    } else {
        cudaLaunchConfig_t cfg = {};
        cfg.gridDim = dim3(NBATCH * 8, 1, 1);
        cfg.blockDim = dim3(512, 1, 1);
        cfg.dynamicSmemBytes = sizeof(SmemT<8, 512>);
        cfg.stream = 0;
        cudaLaunchAttribute attrs[1];
        attrs[0].id = cudaLaunchAttributeClusterDimension;
        attrs[0].val.clusterDim = {8, 1, 1};
        cfg.attrs = attrs;
        cfg.numAttrs = 1;
        cudaLaunchKernelEx(&cfg, fps_kernel<8, 512>, pc, out);
    }
}

// round 7
// speedup vs baseline: 1.9659x; 1.0725x over previous
#include <cuda_runtime.h>
#include <cstdint>

// FPS B=16, N=65536, S=2048, out = coords of selected (B,S,3) f32.
// Cluster of 8 CTAs/batch, 512 thr/CTA. NEGATED coords SoA in smem, loaded as
// ulonglong2 so packed add.rn.f32x2/mul.rn.f32x2 consume aligned reg pairs
// directly (no ALU packing). Per-lane IEEE RN => bit-identical to scalar.
// Value-only max (redux.sync) + parallel-min equality rescan for exact
// first-index argmax; DSMEM push + mbarrier cluster exchange.

#define NBATCH   16
#define NPTS     65536
#define NSAMP    2048
#define CLUSTER  8
#define NPC      (NPTS / CLUSTER)     // 8192
#define THREADS  512
#define NWARPS   (THREADS / 32)       // 16
#define PPT      (NPC / THREADS)      // 16
#define GROUPS   (PPT / 4)            // 4

typedef unsigned long long u64;

// 32-byte slot: key @0 (8-aligned), xy packed @8 (8-aligned), z @16.
struct __align__(16) Slot { u64 key; u64 xy; float z; float pad[3]; };

struct __align__(16) Smem {
    float x[NPC];                // negated coords
    float y[NPC];
    float z[NPC];
    u64   wkey[NWARPS];          // per-warp packed (valBits<<32)|~localIdx
    Slot  slots[2][CLUSTER];     // parity-double-buffered cluster exchange
    u64   mbar;
};

__device__ __forceinline__ uint32_t smem_u32(const void* p) {
    return (uint32_t)__cvta_generic_to_shared(p);
}
__device__ __forceinline__ u64 pk2(float lo, float hi) {
    u64 r; asm("mov.b64 %0, {%1, %2};" : "=l"(r) : "f"(lo), "f"(hi)); return r;
}
__device__ __forceinline__ void upk2(float& lo, float& hi, u64 v) {
    asm("mov.b64 {%0, %1}, %2;" : "=f"(lo), "=f"(hi) : "l"(v));
}
__device__ __forceinline__ u64 add2(u64 a, u64 b) {
    u64 r; asm("add.rn.f32x2 %0, %1, %2;" : "=l"(r) : "l"(a), "l"(b)); return r;
}
__device__ __forceinline__ u64 mul2(u64 a, u64 b) {
    u64 r; asm("mul.rn.f32x2 %0, %1, %2;" : "=l"(r) : "l"(a), "l"(b)); return r;
}

__global__ void __launch_bounds__(THREADS, 2)
fps_kernel(const float* __restrict__ pc, float* __restrict__ out)
{
    extern __shared__ char smraw[];
    Smem& s = *reinterpret_cast<Smem*>(smraw);

    const int tid  = threadIdx.x;
    const int lane = tid & 31;
    const int warp = tid >> 5;
    const int rank = blockIdx.x & (CLUSTER - 1);
    const int b    = blockIdx.x >> 3;

    const float* __restrict__ base = pc + (size_t)b * NPTS * 3;

    // ---- prologue: stage NEGATED coords as SoA ----
    for (int i = tid; i < NPC; i += THREADS) {
        int gi = rank * NPC + i;
        s.x[i] = -base[gi * 3 + 0];
        s.y[i] = -base[gi * 3 + 1];
        s.z[i] = -base[gi * 3 + 2];
    }
    if (tid == 0) {
        asm volatile("mbarrier.init.shared.b64 [%0], %1;"
                     :: "r"(smem_u32(&s.mbar)), "r"(CLUSTER) : "memory");
    }

    float closest[PPT];
    #pragma unroll
    for (int i = 0; i < PPT; i++) closest[i] = __int_as_float(0x7f800000);

    float sx = base[0], sy = base[1], sz = base[2];   // initial selection: point 0

    __syncthreads();
    asm volatile("barrier.cluster.arrive.aligned;" ::: "memory");
    asm volatile("barrier.cluster.wait.aligned;"   ::: "memory");

    const uint32_t mb_addr = smem_u32(&s.mbar);

    for (int it = 0; it < NSAMP; ++it) {
        const int p = it & 1;

        u64 sxx = pk2(sx, sx), syy = pk2(sy, sy), szz = pk2(sz, sz);

        // ---- distance update + running min; value-only max (packed f32x2) ----
        float vmax = 0.0f;
        #pragma unroll
        for (int g = 0; g < GROUPS; ++g) {
            const int bi = g * (THREADS * 4) + tid * 4;
            ulonglong2 X = *reinterpret_cast<const ulonglong2*>(&s.x[bi]);
            ulonglong2 Y = *reinterpret_cast<const ulonglong2*>(&s.y[bi]);
            ulonglong2 Z = *reinterpret_cast<const ulonglong2*>(&s.z[bi]);
            {   // points 0,1 : d = (s + (-x))^2 + (s + (-y))^2 + (s + (-z))^2
                u64 dx = add2(sxx, X.x);
                u64 dy = add2(syy, Y.x);
                u64 dz = add2(szz, Z.x);
                u64 d  = add2(add2(mul2(dx, dx), mul2(dy, dy)), mul2(dz, dz));
                float d0, d1; upk2(d0, d1, d);
                float c0 = fminf(closest[g*4+0], d0); closest[g*4+0] = c0;
                float c1 = fminf(closest[g*4+1], d1); closest[g*4+1] = c1;
                vmax = fmaxf(vmax, c0); vmax = fmaxf(vmax, c1);
            }
            {   // points 2,3
                u64 dx = add2(sxx, X.y);
                u64 dy = add2(syy, Y.y);
                u64 dz = add2(szz, Z.y);
                u64 d  = add2(add2(mul2(dx, dx), mul2(dy, dy)), mul2(dz, dz));
                float d0, d1; upk2(d0, d1, d);
                float c0 = fminf(closest[g*4+2], d0); closest[g*4+2] = c0;
                float c1 = fminf(closest[g*4+3], d1); closest[g*4+3] = c1;
                vmax = fmaxf(vmax, c0); vmax = fmaxf(vmax, c1);
            }
        }

        // ---- warp reduce: redux max on float bits (all >= 0) ----
        unsigned wmax;
        asm("redux.sync.max.u32 %0, %1, 0xffffffff;"
            : "=r"(wmax) : "r"(__float_as_uint(vmax)));

        // exact first index: parallel min over matching indices
        unsigned my = 0xffffffffu;
        #pragma unroll
        for (int g = 0; g < GROUPS; ++g) {
            #pragma unroll
            for (int j = 0; j < 4; ++j) {
                unsigned cand = (unsigned)(g * (THREADS * 4) + tid * 4 + j);
                if (__float_as_uint(closest[g*4+j]) == wmax)
                    my = (cand < my) ? cand : my;
            }
        }
        unsigned wmin;
        asm("redux.sync.min.u32 %0, %1, 0xffffffff;"
            : "=r"(wmin) : "r"(my));
        if (lane == 0)
            s.wkey[warp] = ((u64)wmax << 32) | (u64)(unsigned)(~wmin);
        __syncthreads();

        // ---- CTA reduce (warp 0) + push to all 8 peers ----
        if (warp == 0) {
            u64 k = (lane < NWARPS) ? s.wkey[lane] : 0ull;
            #pragma unroll
            for (int off = 8; off > 0; off >>= 1) {
                u64 o = __shfl_xor_sync(0xffffffffu, k, off);
                if (o > k) k = o;
            }
            // every lane now holds the CTA-best key
            if (lane < CLUSTER) {
                unsigned li   = ~(unsigned)k;                 // local index
                unsigned gidx = (unsigned)rank * NPC + li;    // batch-global index
                u64 ckey = (k & 0xffffffff00000000ull) | (u64)(unsigned)(~gidx);
                float cx = -s.x[li], cy = -s.y[li], cz = -s.z[li];   // un-negate
                u64 xy = pk2(cx, cy);
                uint32_t sl = smem_u32(&s.slots[p][rank]);
                uint32_t rs, rb;
                asm volatile("mapa.shared::cluster.u32 %0, %1, %2;" : "=r"(rs) : "r"(sl),      "r"(lane));
                asm volatile("mapa.shared::cluster.u32 %0, %1, %2;" : "=r"(rb) : "r"(mb_addr), "r"(lane));
                asm volatile("st.shared::cluster.b64 [%0],    %1;" :: "r"(rs), "l"(ckey) : "memory");
                asm volatile("st.shared::cluster.b64 [%0+8],  %1;" :: "r"(rs), "l"(xy)   : "memory");
                asm volatile("st.shared::cluster.f32 [%0+16], %1;" :: "r"(rs), "f"(cz)   : "memory");
                asm volatile("mbarrier.arrive.release.cluster.shared::cluster.b64 _, [%0];"
                             :: "r"(rb) : "memory");
            }
        }

        // ---- wait for all 8 publishes ----
        asm volatile(
            "{\n\t.reg .pred P;\n"
            "W%=:\n\t"
            "mbarrier.try_wait.parity.acquire.cluster.shared::cta.b64 P, [%0], %1, 0x989680;\n\t"
            "@P bra.uni D%=;\n\t"
            "bra.uni W%=;\n"
            "D%=:\n\t}"
            :: "r"(mb_addr), "r"(p) : "memory");

        // ---- scan 8 local slots; winner coords are local ----
        const Slot* sl = s.slots[p];
        u64 bk = sl[0].key;
        int br = 0;
        #pragma unroll
        for (int r = 1; r < CLUSTER; ++r) {
            u64 kr = sl[r].key;
            if (kr > bk) { bk = kr; br = r; }
        }
        float nsx, nsy;
        upk2(nsx, nsy, sl[br].xy);
        float nsz = sl[br].z;

        if (rank == 0 && tid == 0) {
            float* o = out + ((size_t)b * NSAMP + it) * 3;
            o[0] = nsx; o[1] = nsy; o[2] = nsz;
        }
        sx = nsx; sy = nsy; sz = nsz;
    }
}

extern "C" void kernel_launch(void* const* d_in, const int* in_sizes, int n_in,
                              void* d_out, int out_size)
{
    (void)in_sizes; (void)n_in; (void)out_size;
    const float* pc  = (const float*)d_in[0];
    float*       out = (float*)d_out;

    static bool attr_set = false;
    if (!attr_set) {
        cudaFuncSetAttribute(fps_kernel,
                             cudaFuncAttributeMaxDynamicSharedMemorySize,
                             (int)sizeof(Smem));
        attr_set = true;
    }

    cudaLaunchConfig_t cfg = {};
    cfg.gridDim = dim3(NBATCH * CLUSTER, 1, 1);
    cfg.blockDim = dim3(THREADS, 1, 1);
    cfg.dynamicSmemBytes = sizeof(Smem);
    cfg.stream = 0;
    cudaLaunchAttribute attrs[1];
    attrs[0].id = cudaLaunchAttributeClusterDimension;
    attrs[0].val.clusterDim = {CLUSTER, 1, 1};
    cfg.attrs = attrs;
    cfg.numAttrs = 1;
    cudaLaunchKernelEx(&cfg, fps_kernel, pc, out);
}